// round 3
// baseline (speedup 1.0000x reference)
#include <cuda_runtime.h>
#include <math.h>

#define BH 64
#define QL 512
#define KL 4096
#define DD 128
#define RR 32
#define NCH 8
#define CHUNK 512          // KL / NCH
#define NSWEEPS 8
#define PITCH 129          // smem pitch for 128x128 Jacobi matrices

// ---------------- device scratch (static allocation only) ----------------
__device__ float g_Gpart[BH*NCH*DD*DD];   // partial Gram matrices
__device__ float g_mspart[BH*NCH*DD];     // partial column sums
__device__ float g_C[BH*DD*DD];           // centered covariance
__device__ float g_B[BH*DD*RR];           // top-32 eigenbasis  [bh][d][r]
__device__ float g_Kp[(size_t)BH*KL*RR];  // K projected
__device__ float g_Qp[(size_t)BH*QL*RR];  // Q projected (pre-scaled)

// =========================================================================
// Kernel 1: partial Gram  G_chunk = K_chunk^T K_chunk   + column sums
// grid (64, 8), 256 threads.  8x8 register tile per thread.
// =========================================================================
__global__ void gram_partial_kernel(const float* __restrict__ K)
{
    const int bh = blockIdx.x, ch = blockIdx.y;
    const float* Kb = K + ((size_t)bh*KL + (size_t)ch*CHUNK)*DD;

    __shared__ float Ks[16][DD];

    const int tid = threadIdx.x;
    const int ti = tid >> 4, tj = tid & 15;   // 16x16 thread grid
    float acc[8][8];
#pragma unroll
    for (int i = 0; i < 8; i++)
#pragma unroll
        for (int j = 0; j < 8; j++) acc[i][j] = 0.f;
    float cs = 0.f;

    for (int n0 = 0; n0 < CHUNK; n0 += 16) {
        const float4* src = (const float4*)(Kb + (size_t)n0*DD);
        float4* dst = (float4*)(&Ks[0][0]);
#pragma unroll
        for (int i = tid; i < 16*DD/4; i += 256) dst[i] = src[i];
        __syncthreads();

        for (int n = 0; n < 16; n++) {
            float a[8], b[8];
            *(float4*)&a[0] = *(float4*)&Ks[n][ti*8];
            *(float4*)&a[4] = *(float4*)&Ks[n][ti*8+4];
            *(float4*)&b[0] = *(float4*)&Ks[n][tj*8];
            *(float4*)&b[4] = *(float4*)&Ks[n][tj*8+4];
#pragma unroll
            for (int i = 0; i < 8; i++)
#pragma unroll
                for (int j = 0; j < 8; j++) acc[i][j] += a[i]*b[j];
        }
        if (tid < DD) {
#pragma unroll
            for (int n = 0; n < 16; n++) cs += Ks[n][tid];
        }
        __syncthreads();
    }

    float* Gp = g_Gpart + ((size_t)(bh*NCH + ch))*DD*DD;
#pragma unroll
    for (int i = 0; i < 8; i++)
#pragma unroll
        for (int j = 0; j < 8; j++)
            Gp[(ti*8+i)*DD + tj*8+j] = acc[i][j];
    if (tid < DD) g_mspart[(bh*NCH + ch)*DD + tid] = cs;
}

// =========================================================================
// Kernel 2: reduce partials, subtract mean outer product:
//   C = sum(G) - s s^T / KL
// grid 64, 256 threads
// =========================================================================
__global__ void gram_reduce_kernel()
{
    const int bh = blockIdx.x, tid = threadIdx.x;
    __shared__ float s[DD];
    if (tid < DD) {
        float t = 0.f;
#pragma unroll
        for (int c = 0; c < NCH; c++) t += g_mspart[(bh*NCH + c)*DD + tid];
        s[tid] = t;
    }
    __syncthreads();
    const float invn = 1.f/(float)KL;
    for (int e = tid; e < DD*DD; e += 256) {
        const int i = e >> 7, j = e & 127;
        float t = 0.f;
#pragma unroll
        for (int c = 0; c < NCH; c++) t += g_Gpart[((size_t)(bh*NCH + c) << 14) + e];
        g_C[((size_t)bh << 14) + e] = t - s[i]*s[j]*invn;
    }
}

// =========================================================================
// Kernel 3: parallel round-robin Jacobi eigensolver, one block per bh.
// A and V in dynamic smem (pitch 129). Fused 2x2-block similarity update.
// Emits top-32 eigenvectors (arbitrary order — projector is invariant).
// grid 64, 256 threads, 132096 B dynamic smem.
// =========================================================================
__global__ void jacobi_kernel()
{
    extern __shared__ float sm[];
    float* A  = sm;                 // [128][129]
    float* Vm = sm + DD*PITCH;      // [128][129]

    __shared__ int   idx[DD];
    __shared__ int   pr[64], qr[64];
    __shared__ float rc[64], rs[64];
    __shared__ float ev[DD];
    __shared__ int   rank_[DD];

    const int bh = blockIdx.x, tid = threadIdx.x;
    const float* C = g_C + ((size_t)bh << 14);

    for (int e = tid; e < DD*DD; e += 256) {
        const int i = e >> 7, j = e & 127;
        A[i*PITCH + j]  = C[e];
        Vm[i*PITCH + j] = (i == j) ? 1.f : 0.f;
    }
    if (tid < DD) idx[tid] = tid;
    __syncthreads();

    for (int iter = 0; iter < NSWEEPS*127; iter++) {
        // ---- rotation coefficients for 64 disjoint pairs ----
        if (tid < 64) {
            const int p = idx[tid], q = idx[127 - tid];
            const float app = A[p*PITCH + p];
            const float aqq = A[q*PITCH + q];
            const float apq = A[p*PITCH + q];
            float c = 1.f, sv = 0.f;
            if (fabsf(apq) > 1e-10f*(fabsf(app) + fabsf(aqq)) + 1e-35f) {
                const float tau = (aqq - app) / (2.f*apq);
                float t = 1.f / (fabsf(tau) + sqrtf(1.f + tau*tau));
                if (tau < 0.f) t = -t;
                c = rsqrtf(1.f + t*t);
                sv = t*c;
            }
            pr[tid] = p; qr[tid] = q; rc[tid] = c; rs[tid] = sv;
        }
        __syncthreads();

        // ---- A <- J^T A J as disjoint 2x2 blocks (64x64 block items) ----
        for (int it = tid; it < 4096; it += 256) {
            const int m = it >> 6, l = it & 63;
            const int pm = pr[m], qm = qr[m], pl = pr[l], ql = qr[l];
            const float cm = rc[m], smv = rs[m], cl = rc[l], sl = rs[l];
            const float a00 = A[pm*PITCH + pl], a01 = A[pm*PITCH + ql];
            const float a10 = A[qm*PITCH + pl], a11 = A[qm*PITCH + ql];
            const float r00 = cm*a00 - smv*a10, r01 = cm*a01 - smv*a11;
            const float r10 = smv*a00 + cm*a10, r11 = smv*a01 + cm*a11;
            A[pm*PITCH + pl] = cl*r00 - sl*r01;
            A[pm*PITCH + ql] = sl*r00 + cl*r01;
            A[qm*PITCH + pl] = cl*r10 - sl*r11;
            A[qm*PITCH + ql] = sl*r10 + cl*r11;
        }
        // ---- V <- V J (independent of A update) ----
        for (int it = tid; it < 64*DD; it += 256) {
            const int l = it >> 7, k = it & 127;
            const int pl = pr[l], ql = qr[l];
            const float cl = rc[l], sl = rs[l];
            const float vp = Vm[k*PITCH + pl], vq = Vm[k*PITCH + ql];
            Vm[k*PITCH + pl] = cl*vp - sl*vq;
            Vm[k*PITCH + ql] = sl*vp + cl*vq;
        }
        __syncthreads();

        // ---- round-robin rotation of pairing (keep idx[0] fixed) ----
        int v = 0;
        if (tid < DD) v = idx[tid];
        __syncthreads();
        if (tid >= 1 && tid < 127)      idx[tid+1] = v;
        else if (tid == 127)            idx[1]     = v;
        __syncthreads();
    }

    // ---- select top-32 eigenvectors (any order; P = B B^T is invariant) ----
    if (tid < DD) ev[tid] = A[tid*PITCH + tid];
    __syncthreads();
    if (tid < DD) {
        const float e = ev[tid];
        int r_ = 0;
        for (int j = 0; j < DD; j++) {
            const float ej = ev[j];
            if (ej > e || (ej == e && j < tid)) r_++;
        }
        rank_[tid] = r_;
    }
    __syncthreads();
    if (tid < DD && rank_[tid] < RR) {
        const int slot = rank_[tid];
        float* Bb = g_B + (size_t)bh*DD*RR;
        for (int k = 0; k < DD; k++)
            Bb[k*RR + slot] = Vm[k*PITCH + tid];
    }
}

// =========================================================================
// Kernel 4: projection  Y = X * B * scale   (X: [bh][nrows][128] -> Y [..][32])
// grid (64, nrows/64), 256 threads. is_q selects Q vs K path.
// =========================================================================
__global__ void proj_kernel(const float* __restrict__ X, int is_q)
{
    const int bh = blockIdx.x;
    const int t0 = blockIdx.y*64;
    const int nrows = is_q ? QL : KL;
    const float scale = is_q ? 0.17677669529663687f : 1.0f;  // 1/sqrt(32)
    float* Y = is_q ? g_Qp : g_Kp;

    __shared__ float Bs[DD][RR];
    __shared__ float Xs[64][132];   // padded pitch (conflict-free column reads)

    const int tid = threadIdx.x;
    const float* Bsrc = g_B + (size_t)bh*DD*RR;
    for (int i = tid; i < DD*RR/4; i += 256)
        ((float4*)&Bs[0][0])[i] = ((const float4*)Bsrc)[i];

    const float* Xb = X + ((size_t)bh*nrows + t0)*DD;
    for (int i = tid; i < 64*DD/4; i += 256) {
        const int r = i >> 5, c = i & 31;     // 32 float4 per row
        *(float4*)&Xs[r][c*4] = ((const float4*)Xb)[i];
    }
    __syncthreads();

    const int row = tid >> 2, c0 = (tid & 3)*8;
    float acc[8];
#pragma unroll
    for (int j = 0; j < 8; j++) acc[j] = 0.f;

    for (int d = 0; d < DD; d++) {
        const float x = Xs[row][d];
        float b[8];
        *(float4*)&b[0] = *(float4*)&Bs[d][c0];
        *(float4*)&b[4] = *(float4*)&Bs[d][c0+4];
#pragma unroll
        for (int j = 0; j < 8; j++) acc[j] += x*b[j];
    }
    float* Yb = Y + ((size_t)bh*nrows + t0 + row)*RR + c0;
#pragma unroll
    for (int j = 0; j < 8; j++) Yb[j] = acc[j]*scale;
}

// =========================================================================
// Kernel 5: flash attention  out = softmax(Qp Kp^T) V   (all fp32)
// grid (64, 8): TQ=64 q-rows per block, TK=32 kv chunk, 128 threads.
// Each thread accumulates an 8x8 tile of O (64 regs).
// =========================================================================
__global__ void attn_kernel(const float* __restrict__ V, float* __restrict__ Out)
{
    const int bh = blockIdx.x;
    const int q0 = blockIdx.y*64;

    __shared__ float Qs[64][33];
    __shared__ float Ks[32][33];
    __shared__ float Vs[32][132];
    __shared__ float S[64][33];
    __shared__ float mrow[64], lrow[64], scl[64];

    const int tid = threadIdx.x;          // 128 threads
    const int rg = tid >> 4, cg = tid & 15;
    const int r0 = rg*8, c0v = cg*8;      // O tile: rows r0..r0+7, cols c0v..c0v+7
    const int sa = (tid >> 3)*4, sb = (tid & 7)*4;   // S tile: 4x4

    const float* Qp = g_Qp + ((size_t)bh*QL + q0)*RR;
    for (int i = tid; i < 64*RR; i += 128) { const int r = i >> 5, c = i & 31; Qs[r][c] = Qp[i]; }
    if (tid < 64) { mrow[tid] = -1e30f; lrow[tid] = 0.f; }

    float acc[8][8];
#pragma unroll
    for (int i = 0; i < 8; i++)
#pragma unroll
        for (int j = 0; j < 8; j++) acc[i][j] = 0.f;
    __syncthreads();

    for (int kc = 0; kc < KL/32; kc++) {
        const int k0 = kc*32;
        const float* Kp = g_Kp + ((size_t)bh*KL + k0)*RR;
        for (int i = tid; i < 32*RR; i += 128) { const int r = i >> 5, c = i & 31; Ks[r][c] = Kp[i]; }
        const float4* Vb = (const float4*)(V + ((size_t)bh*KL + k0)*DD);
        for (int i = tid; i < 32*DD/4; i += 128) {
            const int r = i >> 5, c = i & 31;
            *(float4*)&Vs[r][c*4] = Vb[i];
        }
        __syncthreads();

        // ---- S = Qp Kp^T (scale pre-folded into Qp) ----
        float s4[4][4];
#pragma unroll
        for (int i = 0; i < 4; i++)
#pragma unroll
            for (int j = 0; j < 4; j++) s4[i][j] = 0.f;
        for (int k = 0; k < RR; k++) {
            float qv[4], kv[4];
#pragma unroll
            for (int i = 0; i < 4; i++) qv[i] = Qs[sa+i][k];
#pragma unroll
            for (int j = 0; j < 4; j++) kv[j] = Ks[sb+j][k];
#pragma unroll
            for (int i = 0; i < 4; i++)
#pragma unroll
                for (int j = 0; j < 4; j++) s4[i][j] += qv[i]*kv[j];
        }
#pragma unroll
        for (int i = 0; i < 4; i++)
#pragma unroll
            for (int j = 0; j < 4; j++) S[sa+i][sb+j] = s4[i][j];
        __syncthreads();

        // ---- online softmax stats: 2 threads per row ----
        {
            const int row = tid >> 1, h = tid & 1;
            float mx = -1e30f;
            for (int c = h*16; c < h*16 + 16; c++) mx = fmaxf(mx, S[row][c]);
            mx = fmaxf(mx, __shfl_xor_sync(0xffffffff, mx, 1));
            const float mold = mrow[row];
            const float mnew = fmaxf(mold, mx);
            float sum = 0.f;
            for (int c = h*16; c < h*16 + 16; c++) {
                const float p = __expf(S[row][c] - mnew);
                S[row][c] = p; sum += p;
            }
            sum += __shfl_xor_sync(0xffffffff, sum, 1);
            if (h == 0) {
                const float sc = __expf(mold - mnew);
                scl[row]  = sc;
                lrow[row] = lrow[row]*sc + sum;
                mrow[row] = mnew;
            }
        }
        __syncthreads();

        // ---- O = O*scale + P V ----
#pragma unroll
        for (int i = 0; i < 8; i++) {
            const float sc = scl[r0+i];
#pragma unroll
            for (int j = 0; j < 8; j++) acc[i][j] *= sc;
        }
        for (int j = 0; j < 32; j++) {
            float vv[8];
            *(float4*)&vv[0] = *(float4*)&Vs[j][c0v];
            *(float4*)&vv[4] = *(float4*)&Vs[j][c0v+4];
#pragma unroll
            for (int i = 0; i < 8; i++) {
                const float p = S[r0+i][j];
#pragma unroll
                for (int jj = 0; jj < 8; jj++) acc[i][jj] += p*vv[jj];
            }
        }
        __syncthreads();
    }

    // ---- epilogue ----
    float* Ob = Out + ((size_t)bh*QL + q0)*DD;
#pragma unroll
    for (int i = 0; i < 8; i++) {
        const float inv = 1.f/lrow[r0+i];
#pragma unroll
        for (int j = 0; j < 8; j++)
            Ob[(r0+i)*DD + c0v + j] = acc[i][j]*inv;
    }
}

// =========================================================================
extern "C" void kernel_launch(void* const* d_in, const int* in_sizes, int n_in,
                              void* d_out, int out_size)
{
    const float* Q = (const float*)d_in[0];
    const float* K = (const float*)d_in[1];
    const float* V = (const float*)d_in[2];
    float* Out = (float*)d_out;

    const int jac_smem = 2*DD*PITCH*(int)sizeof(float);   // 132096 B
    cudaFuncSetAttribute(jacobi_kernel,
                         cudaFuncAttributeMaxDynamicSharedMemorySize, jac_smem);

    gram_partial_kernel<<<dim3(BH, NCH), 256>>>(K);
    gram_reduce_kernel<<<BH, 256>>>();
    jacobi_kernel<<<BH, 256, jac_smem>>>();
    proj_kernel<<<dim3(BH, KL/64), 256>>>(K, 0);
    proj_kernel<<<dim3(BH, QL/64), 256>>>(Q, 1);
    attn_kernel<<<dim3(BH, QL/64), 128>>>(V, Out);
}

// round 4
// speedup vs baseline: 1.2271x; 1.2271x over previous
#include <cuda_runtime.h>
#include <math.h>

#define BH 64
#define QL 512
#define KL 4096
#define DD 128
#define RR 32
#define NCH 8
#define CHUNK 512          // KL / NCH
#define MAXSWEEP 8
#define PITCH 129          // smem pitch for 128x128 Jacobi matrices

// ---------------- device scratch (static allocation only) ----------------
__device__ float g_Gpart[BH*NCH*DD*DD];   // partial Gram matrices
__device__ float g_mspart[BH*NCH*DD];     // partial column sums
__device__ float g_B[BH*DD*RR];           // top-32 eigenbasis  [bh][d][r]
__device__ float g_Kp[(size_t)BH*KL*RR];  // K projected
__device__ float g_Qp[(size_t)BH*QL*RR];  // Q projected (pre-scaled)

// =========================================================================
// Kernel 1: partial Gram  G_chunk = K_chunk^T K_chunk   + column sums
// grid (64, 8), 256 threads.  8x8 register tile per thread.
// =========================================================================
__global__ void gram_partial_kernel(const float* __restrict__ K)
{
    const int bh = blockIdx.x, ch = blockIdx.y;
    const float* Kb = K + ((size_t)bh*KL + (size_t)ch*CHUNK)*DD;

    __shared__ float Ks[16][DD];

    const int tid = threadIdx.x;
    const int ti = tid >> 4, tj = tid & 15;   // 16x16 thread grid
    float acc[8][8];
#pragma unroll
    for (int i = 0; i < 8; i++)
#pragma unroll
        for (int j = 0; j < 8; j++) acc[i][j] = 0.f;
    float cs = 0.f;

    for (int n0 = 0; n0 < CHUNK; n0 += 16) {
        const float4* src = (const float4*)(Kb + (size_t)n0*DD);
        float4* dst = (float4*)(&Ks[0][0]);
#pragma unroll
        for (int i = tid; i < 16*DD/4; i += 256) dst[i] = src[i];
        __syncthreads();

        for (int n = 0; n < 16; n++) {
            float a[8], b[8];
            *(float4*)&a[0] = *(float4*)&Ks[n][ti*8];
            *(float4*)&a[4] = *(float4*)&Ks[n][ti*8+4];
            *(float4*)&b[0] = *(float4*)&Ks[n][tj*8];
            *(float4*)&b[4] = *(float4*)&Ks[n][tj*8+4];
#pragma unroll
            for (int i = 0; i < 8; i++)
#pragma unroll
                for (int j = 0; j < 8; j++) acc[i][j] += a[i]*b[j];
        }
        if (tid < DD) {
#pragma unroll
            for (int n = 0; n < 16; n++) cs += Ks[n][tid];
        }
        __syncthreads();
    }

    float* Gp = g_Gpart + ((size_t)(bh*NCH + ch))*DD*DD;
#pragma unroll
    for (int i = 0; i < 8; i++)
#pragma unroll
        for (int j = 0; j < 8; j++)
            Gp[(ti*8+i)*DD + tj*8+j] = acc[i][j];
    if (tid < DD) g_mspart[(bh*NCH + ch)*DD + tid] = cs;
}

// =========================================================================
// Kernel 2: parallel round-robin Jacobi eigensolver, one block per bh.
//  - Gram reduce + mean-centering fused into the load.
//  - Closed-form tournament pairing (no smem index array, 2 syncs/iter).
//  - Per-sweep convergence early-exit (deterministic).
// grid 64, 512 threads, 132096 B dynamic smem.
// =========================================================================
__global__ void jacobi_kernel()
{
    extern __shared__ float sm[];
    float* A  = sm;                 // [128][129]
    float* Vm = sm + DD*PITCH;      // [128][129]

    __shared__ float ssum[DD];
    __shared__ int   pr[64], qr[64];
    __shared__ float rc[64], rs[64];
    __shared__ float red_o[16], red_d[16];
    __shared__ float ev[DD];
    __shared__ int   rank_[DD];
    __shared__ int   s_done;

    const int bh = blockIdx.x, tid = threadIdx.x;
    const int lane = tid & 31, wid = tid >> 5;

    // ---- fused gram reduce: A = sum_c Gpart - s s^T / KL,  Vm = I ----
    if (tid < DD) {
        float t = 0.f;
#pragma unroll
        for (int c = 0; c < NCH; c++) t += g_mspart[(bh*NCH + c)*DD + tid];
        ssum[tid] = t;
    }
    __syncthreads();
    const float invn = 1.f/(float)KL;
    for (int e = tid; e < DD*DD; e += 512) {
        const int i = e >> 7, j = e & 127;
        float t = 0.f;
#pragma unroll
        for (int c = 0; c < NCH; c++) t += g_Gpart[((size_t)(bh*NCH + c) << 14) + e];
        A[i*PITCH + j]  = t - ssum[i]*ssum[j]*invn;
        Vm[i*PITCH + j] = (i == j) ? 1.f : 0.f;
    }
    __syncthreads();

    int tmod = 0;   // iteration counter mod 127 (tournament phase)
    int done = 0;

    for (int sweep = 0; sweep < MAXSWEEP && !done; sweep++) {
        for (int step = 0; step < 127; step++) {
            // ---- closed-form pairing + rotation coefficients ----
            if (tid < 64) {
                int p;
                if (tid == 0) p = 0;
                else { int r = tid - 1 - tmod; if (r < 0) r += 127; p = 1 + r; }
                int r2 = 126 - tid - tmod; if (r2 < 0) r2 += 127;
                const int q = 1 + r2;

                const float app = A[p*PITCH + p];
                const float aqq = A[q*PITCH + q];
                const float apq = A[p*PITCH + q];
                float c = 1.f, sv = 0.f;
                if (fabsf(apq) > 1e-10f*(fabsf(app) + fabsf(aqq)) + 1e-35f) {
                    const float tau = (aqq - app) / (2.f*apq);
                    float t = 1.f / (fabsf(tau) + sqrtf(1.f + tau*tau));
                    if (tau < 0.f) t = -t;
                    c = rsqrtf(1.f + t*t);
                    sv = t*c;
                }
                pr[tid] = p; qr[tid] = q; rc[tid] = c; rs[tid] = sv;
            }
            __syncthreads();

            // ---- A <- J^T A J as disjoint 2x2 blocks (4096 block items) ----
            for (int it = tid; it < 4096; it += 512) {
                const int m = it >> 6, l = it & 63;
                const int pm = pr[m], qm = qr[m], pl = pr[l], ql = qr[l];
                const float cm = rc[m], smv = rs[m], cl = rc[l], sl = rs[l];
                const float a00 = A[pm*PITCH + pl], a01 = A[pm*PITCH + ql];
                const float a10 = A[qm*PITCH + pl], a11 = A[qm*PITCH + ql];
                const float r00 = cm*a00 - smv*a10, r01 = cm*a01 - smv*a11;
                const float r10 = smv*a00 + cm*a10, r11 = smv*a01 + cm*a11;
                A[pm*PITCH + pl] = cl*r00 - sl*r01;
                A[pm*PITCH + ql] = sl*r00 + cl*r01;
                A[qm*PITCH + pl] = cl*r10 - sl*r11;
                A[qm*PITCH + ql] = sl*r10 + cl*r11;
            }
            // ---- V <- V J ----
            for (int it = tid; it < 64*DD; it += 512) {
                const int l = it >> 7, k = it & 127;
                const int pl = pr[l], ql = qr[l];
                const float cl = rc[l], sl = rs[l];
                const float vp = Vm[k*PITCH + pl], vq = Vm[k*PITCH + ql];
                Vm[k*PITCH + pl] = cl*vp - sl*vq;
                Vm[k*PITCH + ql] = sl*vp + cl*vq;
            }
            __syncthreads();

            if (++tmod == 127) tmod = 0;
        }

        // ---- per-sweep convergence check (deterministic) ----
        float off2 = 0.f, dia2 = 0.f;
        for (int e = tid; e < DD*DD; e += 512) {
            const int i = e >> 7, j = e & 127;
            const float a = A[i*PITCH + j];
            if (i == j) dia2 += a*a; else off2 += a*a;
        }
#pragma unroll
        for (int o = 16; o > 0; o >>= 1) {
            off2 += __shfl_down_sync(0xffffffff, off2, o);
            dia2 += __shfl_down_sync(0xffffffff, dia2, o);
        }
        if (lane == 0) { red_o[wid] = off2; red_d[wid] = dia2; }
        __syncthreads();
        if (tid == 0) {
            float o = 0.f, d = 0.f;
#pragma unroll
            for (int w = 0; w < 16; w++) { o += red_o[w]; d += red_d[w]; }
            s_done = (o <= 1e-10f*d) ? 1 : 0;
        }
        __syncthreads();
        done = s_done;
        __syncthreads();
    }

    // ---- select top-32 eigenvectors (any order; P = B B^T is invariant) ----
    if (tid < DD) ev[tid] = A[tid*PITCH + tid];
    __syncthreads();
    if (tid < DD) {
        const float e = ev[tid];
        int r_ = 0;
        for (int j = 0; j < DD; j++) {
            const float ej = ev[j];
            if (ej > e || (ej == e && j < tid)) r_++;
        }
        rank_[tid] = r_;
    }
    __syncthreads();
    if (tid < DD && rank_[tid] < RR) {
        const int slot = rank_[tid];
        float* Bb = g_B + (size_t)bh*DD*RR;
        for (int k = 0; k < DD; k++)
            Bb[k*RR + slot] = Vm[k*PITCH + tid];
    }
}

// =========================================================================
// Kernel 3: projection  Y = X * B * scale  ([bh][rows][128] -> [..][32])
// grid (64, nrows/128), 256 threads, 2x8 register tile per thread.
// dynamic smem: Xs[128][132] + Bs[128][32] = 83968 B.
// =========================================================================
#define XP 132
__global__ void proj_kernel(const float* __restrict__ X, int is_q)
{
    extern __shared__ float psm[];
    float* Xs = psm;                 // [128][XP]
    float* Bs = psm + 128*XP;        // [128][32]

    const int bh = blockIdx.x;
    const int t0 = blockIdx.y*128;
    const int nrows = is_q ? QL : KL;
    const float scale = is_q ? 0.17677669529663687f : 1.0f;  // 1/sqrt(32)
    float* Y = is_q ? g_Qp : g_Kp;

    const int tid = threadIdx.x;
    const float4* Bsrc = (const float4*)(g_B + (size_t)bh*DD*RR);
    for (int i = tid; i < DD*RR/4; i += 256) ((float4*)Bs)[i] = Bsrc[i];

    const float4* Xb = (const float4*)(X + ((size_t)bh*nrows + t0)*DD);
    for (int i = tid; i < 128*DD/4; i += 256) {
        const int r = i >> 5, c = i & 31;
        *(float4*)&Xs[r*XP + c*4] = Xb[i];
    }
    __syncthreads();

    const int row0 = (tid >> 2)*2, c0 = (tid & 3)*8;
    float a0[8], a1[8];
#pragma unroll
    for (int j = 0; j < 8; j++) { a0[j] = 0.f; a1[j] = 0.f; }

    for (int d = 0; d < DD; d++) {
        const float x0 = Xs[row0*XP + d];
        const float x1 = Xs[(row0+1)*XP + d];
        float b[8];
        *(float4*)&b[0] = *(float4*)&Bs[d*RR + c0];
        *(float4*)&b[4] = *(float4*)&Bs[d*RR + c0 + 4];
#pragma unroll
        for (int j = 0; j < 8; j++) { a0[j] += x0*b[j]; a1[j] += x1*b[j]; }
    }
    float* Yb = Y + ((size_t)bh*nrows + t0 + row0)*RR + c0;
    float4 o0, o1;
    o0.x=a0[0]*scale; o0.y=a0[1]*scale; o0.z=a0[2]*scale; o0.w=a0[3]*scale;
    o1.x=a0[4]*scale; o1.y=a0[5]*scale; o1.z=a0[6]*scale; o1.w=a0[7]*scale;
    *(float4*)&Yb[0] = o0; *(float4*)&Yb[4] = o1;
    o0.x=a1[0]*scale; o0.y=a1[1]*scale; o0.z=a1[2]*scale; o0.w=a1[3]*scale;
    o1.x=a1[4]*scale; o1.y=a1[5]*scale; o1.z=a1[6]*scale; o1.w=a1[7]*scale;
    *(float4*)&Yb[RR] = o0; *(float4*)&Yb[RR+4] = o1;
}

// =========================================================================
// Kernel 4: flash attention  out = softmax(Qp Kp^T) V   (all fp32)
// grid (64, 8): TQ=64 q-rows, TK=32 kv chunk, 128 threads.
// S-compute: 2x8 tiles from transposed Kst (4 LDS : 16 FMA).
// PV: 8x8 register accumulator per thread.
// =========================================================================
#define SP 36
__global__ void attn_kernel(const float* __restrict__ V, float* __restrict__ Out)
{
    const int bh = blockIdx.x;
    const int q0 = blockIdx.y*64;

    __shared__ float Qs[64][33];
    __shared__ float Kst[RR][SP];    // transposed K chunk: [feat][kvrow]
    __shared__ float Vs[32][132];
    __shared__ float S[64][SP];
    __shared__ float mrow[64], lrow[64], scl[64];

    const int tid = threadIdx.x;          // 128 threads
    const int rg = tid >> 4, cg = tid & 15;
    const int r0 = rg*8, c0v = cg*8;      // O tile rows/cols
    const int sa = (tid >> 2)*2, sb = (tid & 3)*8;   // S tile: 2x8

    const float* Qp = g_Qp + ((size_t)bh*QL + q0)*RR;
    for (int i = tid; i < 64*RR; i += 128) { const int r = i >> 5, c = i & 31; Qs[r][c] = Qp[i]; }
    if (tid < 64) { mrow[tid] = -1e30f; lrow[tid] = 0.f; }

    float acc[8][8];
#pragma unroll
    for (int i = 0; i < 8; i++)
#pragma unroll
        for (int j = 0; j < 8; j++) acc[i][j] = 0.f;
    __syncthreads();

    for (int kc = 0; kc < KL/32; kc++) {
        const int k0 = kc*32;
        const float* Kp = g_Kp + ((size_t)bh*KL + k0)*RR;
        for (int i = tid; i < 32*RR; i += 128) {
            const int r = i >> 5, c = i & 31;
            Kst[c][r] = Kp[i];                  // transpose on store (pitch 36)
        }
        const float4* Vb = (const float4*)(V + ((size_t)bh*KL + k0)*DD);
        for (int i = tid; i < 32*DD/4; i += 128) {
            const int r = i >> 5, c = i & 31;
            *(float4*)&Vs[r][c*4] = Vb[i];
        }
        __syncthreads();

        // ---- S = Qp Kp^T (scale pre-folded into Qp), 2x8 tile ----
        float s0[8], s1[8];
#pragma unroll
        for (int j = 0; j < 8; j++) { s0[j] = 0.f; s1[j] = 0.f; }
        for (int k = 0; k < RR; k++) {
            const float qa = Qs[sa][k], qb = Qs[sa+1][k];
            float kv[8];
            *(float4*)&kv[0] = *(float4*)&Kst[k][sb];
            *(float4*)&kv[4] = *(float4*)&Kst[k][sb+4];
#pragma unroll
            for (int j = 0; j < 8; j++) { s0[j] += qa*kv[j]; s1[j] += qb*kv[j]; }
        }
        *(float4*)&S[sa][sb]     = *(float4*)&s0[0];
        *(float4*)&S[sa][sb+4]   = *(float4*)&s0[4];
        *(float4*)&S[sa+1][sb]   = *(float4*)&s1[0];
        *(float4*)&S[sa+1][sb+4] = *(float4*)&s1[4];
        __syncthreads();

        // ---- online softmax stats: 2 threads per row, 16 cols each ----
        {
            const int row = tid >> 1, h = tid & 1;
            float mx = -1e30f;
            for (int c = h*16; c < h*16 + 16; c++) mx = fmaxf(mx, S[row][c]);
            mx = fmaxf(mx, __shfl_xor_sync(0xffffffff, mx, 1));
            const float mold = mrow[row];
            const float mnew = fmaxf(mold, mx);
            float sum = 0.f;
            for (int c = h*16; c < h*16 + 16; c++) {
                const float p = __expf(S[row][c] - mnew);
                S[row][c] = p; sum += p;
            }
            sum += __shfl_xor_sync(0xffffffff, sum, 1);
            if (h == 0) {
                const float sc = __expf(mold - mnew);
                scl[row]  = sc;
                lrow[row] = lrow[row]*sc + sum;
                mrow[row] = mnew;
            }
        }
        __syncthreads();

        // ---- O = O*scale + P V ----
#pragma unroll
        for (int i = 0; i < 8; i++) {
            const float sc = scl[r0+i];
#pragma unroll
            for (int j = 0; j < 8; j++) acc[i][j] *= sc;
        }
        for (int j = 0; j < 32; j++) {
            float vv[8];
            *(float4*)&vv[0] = *(float4*)&Vs[j][c0v];
            *(float4*)&vv[4] = *(float4*)&Vs[j][c0v+4];
#pragma unroll
            for (int i = 0; i < 8; i++) {
                const float p = S[r0+i][j];
#pragma unroll
                for (int jj = 0; jj < 8; jj++) acc[i][jj] += p*vv[jj];
            }
        }
        __syncthreads();
    }

    // ---- epilogue (float4 stores) ----
    float* Ob = Out + ((size_t)bh*QL + q0)*DD;
#pragma unroll
    for (int i = 0; i < 8; i++) {
        const float inv = 1.f/lrow[r0+i];
        float4 o0, o1;
        o0.x=acc[i][0]*inv; o0.y=acc[i][1]*inv; o0.z=acc[i][2]*inv; o0.w=acc[i][3]*inv;
        o1.x=acc[i][4]*inv; o1.y=acc[i][5]*inv; o1.z=acc[i][6]*inv; o1.w=acc[i][7]*inv;
        *(float4*)&Ob[(r0+i)*DD + c0v]     = o0;
        *(float4*)&Ob[(r0+i)*DD + c0v + 4] = o1;
    }
}

// =========================================================================
extern "C" void kernel_launch(void* const* d_in, const int* in_sizes, int n_in,
                              void* d_out, int out_size)
{
    const float* Q = (const float*)d_in[0];
    const float* K = (const float*)d_in[1];
    const float* V = (const float*)d_in[2];
    float* Out = (float*)d_out;

    const int jac_smem = 2*DD*PITCH*(int)sizeof(float);        // 132096 B
    const int proj_smem = (128*XP + 128*RR)*(int)sizeof(float); // 83968 B
    cudaFuncSetAttribute(jacobi_kernel,
                         cudaFuncAttributeMaxDynamicSharedMemorySize, jac_smem);
    cudaFuncSetAttribute(proj_kernel,
                         cudaFuncAttributeMaxDynamicSharedMemorySize, proj_smem);

    gram_partial_kernel<<<dim3(BH, NCH), 256>>>(K);
    jacobi_kernel<<<BH, 512, jac_smem>>>();
    proj_kernel<<<dim3(BH, KL/128), 256, proj_smem>>>(K, 0);
    proj_kernel<<<dim3(BH, QL/128), 256, proj_smem>>>(Q, 1);
    attn_kernel<<<dim3(BH, QL/64), 128>>>(V, Out);
}